// round 15
// baseline (speedup 1.0000x reference)
#include <cuda_runtime.h>
#include <cuda_fp16.h>
#include <cstdint>
#include <cstddef>

// ---------------------------------------------------------------------------
// Problem constants
// ---------------------------------------------------------------------------
#define BB_ 4
#define TT_ 4096
#define DD_ 1024
#define MM_ (BB_ * TT_)   // 16384 rows
#define E3_ (3 * DD_)     // 3072

// ---------------------------------------------------------------------------
// Scratch (static device globals -- allocation-free rule)
// ---------------------------------------------------------------------------
__device__ __half g_qh[(size_t)MM_ * DD_];     // q fp16 (GEMM1 epilogue)
__device__ __half g_kh[(size_t)MM_ * DD_];     // k fp16
__device__ __half g_vh[(size_t)MM_ * DD_];     // v fp16
__device__ __half g_xh[(size_t)MM_ * DD_];     // x fp16
__device__ __half g_wqh[(size_t)E3_ * DD_];
__device__ __half g_woh[(size_t)DD_ * DD_];
__device__ __half g_wp[(size_t)BB_ * DD_ * DD_];  // per-batch Wout*kv fp16
__device__ float g_sq[MM_];                    // sum q^2 per row (atomics)
__device__ float g_sk[MM_];                    // sum k^2 per row (atomics)
__device__ float g_invq[MM_];
__device__ float g_kv[BB_ * DD_];
__device__ int   g_mask_is_byte;

// ---------------------------------------------------------------------------
// Helpers (sm_103 baseline ISA: cp.async, ldmatrix, mma.sync)
// ---------------------------------------------------------------------------
__device__ __forceinline__ uint32_t smem_to_u32(const void* smem_ptr) {
    uint32_t addr;
    asm("{ .reg .u64 tmp; cvta.to.shared.u64 tmp, %1; cvt.u32.u64 %0, tmp; }"
        : "=r"(addr) : "l"(smem_ptr));
    return addr;
}

__device__ __forceinline__ void cp16(uint32_t smem_dst, const void* gmem_src) {
    asm volatile("cp.async.cg.shared.global [%0], [%1], 16;\n"
                 :: "r"(smem_dst), "l"(gmem_src));
}
#define CP_ASYNC_COMMIT() asm volatile("cp.async.commit_group;\n" ::: "memory")
#define CP_ASYNC_WAIT_1() asm volatile("cp.async.wait_group 1;\n" ::: "memory")
#define CP_ASYNC_WAIT_0() asm volatile("cp.async.wait_group 0;\n" ::: "memory")

#define LDSM_X4(r0, r1, r2, r3, addr) \
    asm volatile("ldmatrix.sync.aligned.m8n8.x4.shared.b16 {%0,%1,%2,%3}, [%4];" \
                 : "=r"(r0), "=r"(r1), "=r"(r2), "=r"(r3) : "r"(addr))

// fp16 MMA with fp32 accumulate
#define MMA_16816_F16(c, a, b) \
    asm volatile("mma.sync.aligned.m16n8k16.row.col.f32.f16.f16.f32 " \
                 "{%0,%1,%2,%3}, {%4,%5,%6,%7}, {%8,%9}, {%0,%1,%2,%3};" \
                 : "+f"((c)[0]), "+f"((c)[1]), "+f"((c)[2]), "+f"((c)[3]) \
                 : "r"((a)[0]), "r"((a)[1]), "r"((a)[2]), "r"((a)[3]), \
                   "r"((b)[0]), "r"((b)[1]))

#define SMEM_SWIZZLE_128B(byte_offset) \
    ((byte_offset) ^ (((byte_offset) >> 3) & 0x70))

// ---------------------------------------------------------------------------
// fp16 GEMM: CTA tile 128x128, BK=64; 128 thr = 4 warps 2(M)x2(N), warp 64x64.
// Stage: [A 16KB][B 16KB] = 32KB; 3-stage ring = 96KB -> 2 CTAs/SM.
// MODE 1 (qkv GEMM): q/k/v tiles -> fp16 buffers (stride 1024 each);
//   q/k row sumsq fused via atomics.
// MODE 2 (out GEMM): B is per-batch Wp (offset m0>>12 * 1MB elems);
//   C = invq[r] * (A @ B^T) + bias -> fp32.
// ---------------------------------------------------------------------------
#define STAGES 3
#define STAGE_BYTES 32768
#define GS_TOTAL (STAGES * STAGE_BYTES)   // 98304 (2 CTAs -> 192KB/SM)
#define NKT 16                            // 1024 / 64
#define NTHR 128

__device__ __forceinline__ void gemm_issue_load(
    uint32_t sb, int slot, int tid, int m0, int n0, int k0,
    const __half* __restrict__ A, const __half* __restrict__ B)
{
    uint32_t base = sb + slot * STAGE_BYTES;
    #pragma unroll
    for (int i = 0; i < 8; i++) {           // A: 128 rows x 8 chunks = 1024
        int id = tid + (i << 7);
        int r  = id >> 3;
        int cc = id & 7;
        uint32_t soff = SMEM_SWIZZLE_128B((uint32_t)((r << 7) + (cc << 4)));
        cp16(base + soff, A + (size_t)(m0 + r) * DD_ + k0 + (cc << 3));
    }
    #pragma unroll
    for (int i = 0; i < 8; i++) {           // B: 128 rows x 8 chunks = 1024
        int id = tid + (i << 7);
        int r  = id >> 3;
        int cc = id & 7;
        uint32_t soff = SMEM_SWIZZLE_128B((uint32_t)((r << 7) + (cc << 4)));
        cp16(base + 16384 + soff, B + (size_t)(n0 + r) * DD_ + k0 + (cc << 3));
    }
    CP_ASYNC_COMMIT();
}

template <int MODE>
__global__ __launch_bounds__(NTHR, 2) void gemm_f16_kernel(
    const __half* __restrict__ A, const __half* __restrict__ B,
    const float* __restrict__ bias, float* __restrict__ C, int N,
    __half* __restrict__ Cq, __half* __restrict__ Ck, __half* __restrict__ Cv,
    float* __restrict__ sq, float* __restrict__ sk)
{
    extern __shared__ char smem[];
    uint32_t sb = smem_to_u32(smem);
    const int tid = threadIdx.x;
    const int wid = tid >> 5;
    const int lane = tid & 31;
    const int n0 = blockIdx.x * 128;   // N fast-varying: wave shares A via L2
    const int m0 = blockIdx.y * 128;
    const int warp_m = (wid & 1) * 64;     // 2 M-groups of 64
    const int warp_n = (wid >> 1) * 64;    // 2 N-groups of 64

    // MODE 2: per-batch B (Wout * kv[batch]) selected by row block
    const __half* __restrict__ Bp = (MODE == 2)
        ? B + ((size_t)(m0 >> 12) << 20) : B;

    // ldmatrix per-lane address components (validated R2-R14)
    const int lr = lane & 7;
    const int a_row = warp_m + lr + ((lane & 8) ? 8 : 0);
    const int a_ksel = (lane & 16) ? 16 : 0;
    const int b_row = warp_n + lr + ((lane & 16) ? 8 : 0);
    const int b_ksel = (lane & 8) ? 16 : 0;

    float acc[4][8][4];
    #pragma unroll
    for (int i = 0; i < 4; i++)
        #pragma unroll
        for (int j = 0; j < 8; j++)
            #pragma unroll
            for (int k = 0; k < 4; k++) acc[i][j][k] = 0.0f;

    // prologue: stages 0,1
    gemm_issue_load(sb, 0, tid, m0, n0, 0,  A, Bp);
    gemm_issue_load(sb, 1, tid, m0, n0, 64, A, Bp);

    int slot = 0;
    for (int it = 0; it < NKT; it++) {
        if (it == NKT - 1) { CP_ASYNC_WAIT_0(); } else { CP_ASYNC_WAIT_1(); }
        __syncthreads();

        int nt = it + 2;
        if (nt < NKT) {
            int ns = slot + 2; if (ns >= STAGES) ns -= STAGES;
            gemm_issue_load(sb, ns, tid, m0, n0, nt << 6, A, Bp);
        }

        uint32_t ab = sb + slot * STAGE_BYTES;
        uint32_t bb = ab + 16384;

        #pragma unroll
        for (int ks = 0; ks < 4; ks++) {
            uint32_t koff = (uint32_t)(ks << 5);
            uint32_t bfr[8][2];
            #pragma unroll
            for (int nb = 0; nb < 4; nb++) {
                int row = b_row + nb * 16;
                uint32_t addr = bb + (uint32_t)(row << 7)
                              + ((koff + b_ksel) ^ (uint32_t)((row & 7) << 4));
                LDSM_X4(bfr[2 * nb][0], bfr[2 * nb][1],
                        bfr[2 * nb + 1][0], bfr[2 * nb + 1][1], addr);
            }
            uint32_t afr[4][4];
            #pragma unroll
            for (int mf = 0; mf < 4; mf++) {
                int row = a_row + mf * 16;
                uint32_t addr = ab + (uint32_t)(row << 7)
                              + ((koff + a_ksel) ^ (uint32_t)((row & 7) << 4));
                LDSM_X4(afr[mf][0], afr[mf][1], afr[mf][2], afr[mf][3], addr);
            }
            #pragma unroll
            for (int mf = 0; mf < 4; mf++)
                #pragma unroll
                for (int nf = 0; nf < 8; nf++)
                    MMA_16816_F16(acc[mf][nf], afr[mf], bfr[nf]);
        }
        slot++; if (slot >= STAGES) slot = 0;
    }

    // epilogue
    const int gid = lane >> 2;
    const int t4 = lane & 3;
    const int blk = n0 >> 10;            // MODE 1: 0=q, 1=k, 2=v (uniform per CTA)
    const int ncl = n0 & 1023;           // column base within q/k/v buffer
    __half* __restrict__ H = (MODE == 1)
        ? ((blk == 0) ? Cq : (blk == 1) ? Ck : Cv) : (__half*)nullptr;
    #pragma unroll
    for (int mf = 0; mf < 4; mf++) {
        int r0 = m0 + warp_m + mf * 16 + gid;
        float iq0 = 1.f, iq1 = 1.f;
        if (MODE == 2) { iq0 = sq[r0]; iq1 = sq[r0 + 8]; }   // sq carries invq
        float s0 = 0.f, s1 = 0.f;
        #pragma unroll
        for (int nf = 0; nf < 8; nf++) {
            int c = n0 + warp_n + nf * 8 + t4 * 2;
            float2 b2 = *(const float2*)(bias + c);
            if (MODE == 2) {
                float z00 = acc[mf][nf][0] * iq0 + b2.x;
                float z01 = acc[mf][nf][1] * iq0 + b2.y;
                float z10 = acc[mf][nf][2] * iq1 + b2.x;
                float z11 = acc[mf][nf][3] * iq1 + b2.y;
                *(float2*)(C + (size_t)r0 * N + c) = make_float2(z00, z01);
                *(float2*)(C + (size_t)(r0 + 8) * N + c) = make_float2(z10, z11);
            } else {
                float z00 = acc[mf][nf][0] + b2.x;
                float z01 = acc[mf][nf][1] + b2.y;
                float z10 = acc[mf][nf][2] + b2.x;
                float z11 = acc[mf][nf][3] + b2.y;
                int cl = ncl + warp_n + nf * 8 + t4 * 2;
                *(__half2*)(H + (size_t)r0 * DD_ + cl) = __floats2half2_rn(z00, z01);
                *(__half2*)(H + (size_t)(r0 + 8) * DD_ + cl) = __floats2half2_rn(z10, z11);
                s0 += z00 * z00 + z01 * z01;
                s1 += z10 * z10 + z11 * z11;
            }
        }
        if (MODE == 1 && blk < 2) {
            // reduce across the 4 t4-lanes sharing this row pair
            s0 += __shfl_xor_sync(0xffffffffu, s0, 1);
            s0 += __shfl_xor_sync(0xffffffffu, s0, 2);
            s1 += __shfl_xor_sync(0xffffffffu, s1, 1);
            s1 += __shfl_xor_sync(0xffffffffu, s1, 2);
            if (t4 == 0) {
                float* dst = (blk == 0) ? sq : sk;
                atomicAdd(dst + r0, s0);
                atomicAdd(dst + r0 + 8, s1);
            }
        }
    }
}

// ---------------------------------------------------------------------------
// Elementwise / reduction kernels
// ---------------------------------------------------------------------------

// fp32 -> fp16 convert, 8 elems/thread (x buffer)
__global__ void cvt_f16_kernel(const float* __restrict__ in,
                               __half* __restrict__ out, int n8)
{
    int idx = blockIdx.x * blockDim.x + threadIdx.x;
    if (idx >= n8) return;
    float4 a = ((const float4*)in)[idx * 2];
    float4 b = ((const float4*)in)[idx * 2 + 1];
    union { uint4 u; __half2 h[4]; } r;
    r.h[0] = __floats2half2_rn(a.x, a.y);
    r.h[1] = __floats2half2_rn(a.z, a.w);
    r.h[2] = __floats2half2_rn(b.x, b.y);
    r.h[3] = __floats2half2_rn(b.z, b.w);
    ((uint4*)out)[idx] = r.u;
}

// Both weight matrices in one launch: chunks [0, NWQ) -> Wqkv, rest -> Wout.
#define NWQ_ (E3_ * DD_ / 8)
#define NWO_ (DD_ * DD_ / 8)
__global__ void cvt_w_kernel(const float* __restrict__ wq,
                             const float* __restrict__ wo,
                             __half* __restrict__ wqh,
                             __half* __restrict__ woh)
{
    int idx = blockIdx.x * blockDim.x + threadIdx.x;
    const float* in;
    __half* out;
    int off;
    if (idx < NWQ_) { in = wq; out = wqh; off = idx; }
    else            { in = wo; out = woh; off = idx - NWQ_; }
    float4 a = ((const float4*)in)[off * 2];
    float4 b = ((const float4*)in)[off * 2 + 1];
    union { uint4 u; __half2 h[4]; } r;
    r.h[0] = __floats2half2_rn(a.x, a.y);
    r.h[1] = __floats2half2_rn(a.z, a.w);
    r.h[2] = __floats2half2_rn(b.x, b.y);
    r.h[3] = __floats2half2_rn(b.z, b.w);
    ((uint4*)out)[off] = r.u;
}

// zero kv + sumsq buffers AND detect mask dtype (one launch; 64 blocks)
__global__ void prep_kernel(float* __restrict__ kv,
                            float* __restrict__ sq, float* __restrict__ sk,
                            const unsigned char* __restrict__ m)
{
    int i = blockIdx.x * blockDim.x + threadIdx.x;
    if (i < BB_ * DD_) kv[i] = 0.0f;
    if (i < MM_) { sq[i] = 0.0f; sk[i] = 0.0f; }
    if (blockIdx.x == 0) {
        __shared__ int any;
        if (threadIdx.x == 0) any = 0;
        __syncthreads();
        int acc = 0;
        for (int j = threadIdx.x; j < MM_; j += blockDim.x)
            if ((j & 3) != 0) acc |= m[j];
        if (acc) atomicOr(&any, 1);
        __syncthreads();
        if (threadIdx.x == 0) g_mask_is_byte = any ? 1 : 0;
    }
}

// Masked k_hat*v reduction into kv[B,D]; invq from precomputed sumsq.
// Block = 64 rows, 256 threads; thread owns dims [4*tid, 4*tid+4).
__global__ __launch_bounds__(256) void stage2_kernel(
    const __half* __restrict__ kh, const __half* __restrict__ vh,
    const unsigned char* __restrict__ mask,
    const float* __restrict__ sq, const float* __restrict__ sk,
    float* __restrict__ invq, float* __restrict__ kv)
{
    __shared__ float s_ik[64];
    int tid = threadIdx.x;
    int R0 = blockIdx.x * 64;
    int b = R0 >> 12;
    int maskIsByte = g_mask_is_byte;
    const int* mask32 = (const int*)mask;

    if (tid < 64) {
        int row = R0 + tid;
        invq[row] = rsqrtf(sq[row]);
        s_ik[tid] = rsqrtf(sk[row]);
    }
    __syncthreads();

    float ax = 0.f, ay = 0.f, az = 0.f, aw = 0.f;
    for (int r = 0; r < 64; r++) {
        int row = R0 + r;
        bool msk = maskIsByte ? (mask[row] != 0) : (mask32[row] != 0);
        if (!msk) {
            float ik = s_ik[r];
            union { uint2 u; __half2 h[2]; } kk, vv;
            kk.u = *(const uint2*)(kh + (size_t)row * DD_ + tid * 4);
            vv.u = *(const uint2*)(vh + (size_t)row * DD_ + tid * 4);
            float2 k0 = __half22float2(kk.h[0]);
            float2 k1 = __half22float2(kk.h[1]);
            float2 v0 = __half22float2(vv.h[0]);
            float2 v1 = __half22float2(vv.h[1]);
            ax += k0.x * ik * v0.x;
            ay += k0.y * ik * v0.y;
            az += k1.x * ik * v1.x;
            aw += k1.y * ik * v1.y;
        }
    }
    float* kvb = kv + b * DD_ + tid * 4;
    atomicAdd(kvb + 0, ax);
    atomicAdd(kvb + 1, ay);
    atomicAdd(kvb + 2, az);
    atomicAdd(kvb + 3, aw);
}

// Wp[b][n][c] = Wout[n][c] * kv[b][c]  -> fp16. 8 elems/thread.
__global__ __launch_bounds__(256) void build_wp_kernel(
    const __half* __restrict__ woh, const float* __restrict__ kv,
    __half* __restrict__ wp)
{
    int idx = blockIdx.x * blockDim.x + threadIdx.x;   // 8-elem chunk id
    int b = idx >> 17;                // (1024*1024/8) = 131072 chunks per batch
    int off = idx & 131071;
    int c = (off & 127) * 8;          // column within row
    union { uint4 u; __half2 h[4]; } w;
    w.u = *(const uint4*)(woh + (size_t)off * 8);
    const float* kp = kv + b * DD_ + c;
    float4 k0 = *(const float4*)(kp);
    float4 k1 = *(const float4*)(kp + 4);
    float2 w0 = __half22float2(w.h[0]);
    float2 w1 = __half22float2(w.h[1]);
    float2 w2 = __half22float2(w.h[2]);
    float2 w3 = __half22float2(w.h[3]);
    union { uint4 u; __half2 h[4]; } r;
    r.h[0] = __floats2half2_rn(w0.x * k0.x, w0.y * k0.y);
    r.h[1] = __floats2half2_rn(w1.x * k0.z, w1.y * k0.w);
    r.h[2] = __floats2half2_rn(w2.x * k1.x, w2.y * k1.y);
    r.h[3] = __floats2half2_rn(w3.x * k1.z, w3.y * k1.w);
    *(uint4*)(wp + (size_t)idx * 8) = r.u;
}

// ---------------------------------------------------------------------------
// Launch
// ---------------------------------------------------------------------------
extern "C" void kernel_launch(void* const* d_in, const int* in_sizes, int n_in,
                              void* d_out, int out_size)
{
    const float* x = (const float*)d_in[0];
    const unsigned char* mask = (const unsigned char*)d_in[1];
    const float* Wqkv = (const float*)d_in[2];
    const float* bqkv = (const float*)d_in[3];
    const float* Wout = (const float*)d_in[4];
    const float* bout = (const float*)d_in[5];
    float* out = (float*)d_out;

    float *p_invq, *p_kv, *p_sq, *p_sk;
    __half *p_qh, *p_kh, *p_vh, *p_xh, *p_wqh, *p_woh, *p_wp;
    cudaGetSymbolAddress((void**)&p_invq, g_invq);
    cudaGetSymbolAddress((void**)&p_kv, g_kv);
    cudaGetSymbolAddress((void**)&p_sq, g_sq);
    cudaGetSymbolAddress((void**)&p_sk, g_sk);
    cudaGetSymbolAddress((void**)&p_qh, g_qh);
    cudaGetSymbolAddress((void**)&p_kh, g_kh);
    cudaGetSymbolAddress((void**)&p_vh, g_vh);
    cudaGetSymbolAddress((void**)&p_xh, g_xh);
    cudaGetSymbolAddress((void**)&p_wqh, g_wqh);
    cudaGetSymbolAddress((void**)&p_woh, g_woh);
    cudaGetSymbolAddress((void**)&p_wp, g_wp);

    cudaFuncSetAttribute(gemm_f16_kernel<1>,
                         cudaFuncAttributeMaxDynamicSharedMemorySize, GS_TOTAL);
    cudaFuncSetAttribute(gemm_f16_kernel<2>,
                         cudaFuncAttributeMaxDynamicSharedMemorySize, GS_TOTAL);

    // 1: zero buffers + mask dtype detection
    prep_kernel<<<MM_ / 256, 256>>>(p_kv, p_sq, p_sk, mask);
    // 2: x -> fp16
    cvt_f16_kernel<<<(MM_ * DD_ / 8 + 255) / 256, 256>>>(x, p_xh, MM_ * DD_ / 8);
    // 3: Wqkv + Wout -> fp16 (single launch)
    cvt_w_kernel<<<(NWQ_ + NWO_ + 255) / 256, 256>>>(Wqkv, Wout, p_wqh, p_woh);
    // 4: GEMM1: qkv = x @ W_qkv^T + b_qkv; q/k/v -> fp16, norms fused
    gemm_f16_kernel<1><<<dim3(E3_ / 128, MM_ / 128), NTHR, GS_TOTAL>>>(
        p_xh, p_wqh, bqkv, (float*)nullptr, E3_, p_qh, p_kh, p_vh, p_sq, p_sk);
    // 5: masked k_hat*v reduction -> kv
    stage2_kernel<<<MM_ / 64, 256>>>(p_kh, p_vh, mask, p_sq, p_sk, p_invq, p_kv);
    // 6: Wp[b] = Wout * kv[b]
    build_wp_kernel<<<BB_ * DD_ * DD_ / 8 / 256, 256>>>(p_woh, p_kv, p_wp);
    // 7: GEMM2: out = invq * (q @ Wp_b^T) + b_out
    gemm_f16_kernel<2><<<dim3(DD_ / 128, MM_ / 128), NTHR, GS_TOTAL>>>(
        p_qh, p_wp, bout, out, DD_, (__half*)nullptr, (__half*)nullptr,
        (__half*)nullptr, p_invq, nullptr);
}

// round 16
// speedup vs baseline: 1.2038x; 1.2038x over previous
#include <cuda_runtime.h>
#include <cuda_fp16.h>
#include <cstdint>
#include <cstddef>

// ---------------------------------------------------------------------------
// Problem constants
// ---------------------------------------------------------------------------
#define BB_ 4
#define TT_ 4096
#define DD_ 1024
#define MM_ (BB_ * TT_)   // 16384 rows
#define E3_ (3 * DD_)     // 3072

// ---------------------------------------------------------------------------
// Scratch (static device globals -- allocation-free rule)
// ---------------------------------------------------------------------------
__device__ __half g_qh[(size_t)MM_ * DD_];     // q fp16 (all rows)
__device__ __half g_kh[(size_t)MM_ * DD_];     // k fp16 (compacted rows)
__device__ __half g_vh[(size_t)MM_ * DD_];     // v fp16 (compacted rows)
__device__ __half g_xh[(size_t)MM_ * DD_];     // x fp16
__device__ __half g_wqh[(size_t)E3_ * DD_];
__device__ __half g_woh[(size_t)DD_ * DD_];
__device__ __half g_wp[(size_t)BB_ * DD_ * DD_];  // per-batch Wout*kv fp16
__device__ float g_sq[MM_];                    // sum q^2 per row (atomics)
__device__ float g_sk[MM_];                    // sum k^2 per compacted row
__device__ float g_kv[BB_ * DD_];
__device__ int   g_rowmap[MM_];                // unmasked original row ids
__device__ int   g_cnt;                        // # unmasked rows
__device__ int   g_cnt_pad;                    // rounded up to 128

// ---------------------------------------------------------------------------
// Helpers (sm_103 baseline ISA: cp.async, ldmatrix, mma.sync)
// ---------------------------------------------------------------------------
__device__ __forceinline__ uint32_t smem_to_u32(const void* smem_ptr) {
    uint32_t addr;
    asm("{ .reg .u64 tmp; cvta.to.shared.u64 tmp, %1; cvt.u32.u64 %0, tmp; }"
        : "=r"(addr) : "l"(smem_ptr));
    return addr;
}

__device__ __forceinline__ void cp16(uint32_t smem_dst, const void* gmem_src) {
    asm volatile("cp.async.cg.shared.global [%0], [%1], 16;\n"
                 :: "r"(smem_dst), "l"(gmem_src));
}
#define CP_ASYNC_COMMIT() asm volatile("cp.async.commit_group;\n" ::: "memory")
#define CP_ASYNC_WAIT_1() asm volatile("cp.async.wait_group 1;\n" ::: "memory")
#define CP_ASYNC_WAIT_0() asm volatile("cp.async.wait_group 0;\n" ::: "memory")

#define LDSM_X4(r0, r1, r2, r3, addr) \
    asm volatile("ldmatrix.sync.aligned.m8n8.x4.shared.b16 {%0,%1,%2,%3}, [%4];" \
                 : "=r"(r0), "=r"(r1), "=r"(r2), "=r"(r3) : "r"(addr))

// fp16 MMA with fp32 accumulate
#define MMA_16816_F16(c, a, b) \
    asm volatile("mma.sync.aligned.m16n8k16.row.col.f32.f16.f16.f32 " \
                 "{%0,%1,%2,%3}, {%4,%5,%6,%7}, {%8,%9}, {%0,%1,%2,%3};" \
                 : "+f"((c)[0]), "+f"((c)[1]), "+f"((c)[2]), "+f"((c)[3]) \
                 : "r"((a)[0]), "r"((a)[1]), "r"((a)[2]), "r"((a)[3]), \
                   "r"((b)[0]), "r"((b)[1]))

#define SMEM_SWIZZLE_128B(byte_offset) \
    ((byte_offset) ^ (((byte_offset) >> 3) & 0x70))

// ---------------------------------------------------------------------------
// fp16 GEMM: CTA tile 128x128, BK=64; 128 thr = 4 warps 2(M)x2(N), warp 64x64.
// Stage: [A 16KB][B 16KB] = 32KB; 3-stage ring = 96KB -> 2 CTAs/SM.
// MODE 1 (q GEMM): all rows, N=1024; q -> fp16 H0; row sumsq -> snorm.
// MODE 3 (kv GEMM): A rows via rowmap (compacted), N=2048; k -> H0, v -> H1
//   at compacted row index; k sumsq -> snorm. CTAs beyond g_cnt_pad exit.
// MODE 2 (out GEMM): B per-batch Wp (offset m0>>12); C = rsqrt(snorm[r]) *
//   (A @ B^T) + bias -> fp32.
// ---------------------------------------------------------------------------
#define STAGES 3
#define STAGE_BYTES 32768
#define GS_TOTAL (STAGES * STAGE_BYTES)   // 98304 (2 CTAs -> 192KB/SM)
#define NKT 16                            // 1024 / 64
#define NTHR 128

template <int MODE>
__device__ __forceinline__ void gemm_issue_load(
    uint32_t sb, int slot, int tid, int m0, int n0, int k0,
    const __half* __restrict__ A, const __half* __restrict__ B,
    const int* __restrict__ rmap)
{
    uint32_t base = sb + slot * STAGE_BYTES;
    #pragma unroll
    for (int i = 0; i < 8; i++) {           // A: 128 rows x 8 chunks = 1024
        int id = tid + (i << 7);
        int r  = id >> 3;
        int cc = id & 7;
        int ra = (MODE == 3) ? rmap[m0 + r] : (m0 + r);
        uint32_t soff = SMEM_SWIZZLE_128B((uint32_t)((r << 7) + (cc << 4)));
        cp16(base + soff, A + (size_t)ra * DD_ + k0 + (cc << 3));
    }
    #pragma unroll
    for (int i = 0; i < 8; i++) {           // B: 128 rows x 8 chunks = 1024
        int id = tid + (i << 7);
        int r  = id >> 3;
        int cc = id & 7;
        uint32_t soff = SMEM_SWIZZLE_128B((uint32_t)((r << 7) + (cc << 4)));
        cp16(base + 16384 + soff, B + (size_t)(n0 + r) * DD_ + k0 + (cc << 3));
    }
    CP_ASYNC_COMMIT();
}

template <int MODE>
__global__ __launch_bounds__(NTHR, 2) void gemm_f16_kernel(
    const __half* __restrict__ A, const __half* __restrict__ B,
    const float* __restrict__ bias, float* __restrict__ C, int N,
    __half* __restrict__ H0, __half* __restrict__ H1,
    float* __restrict__ snorm, const int* __restrict__ rmap)
{
    const int n0 = blockIdx.x * 128;   // N fast-varying: wave shares A via L2
    const int m0 = blockIdx.y * 128;
    if (MODE == 3) { if (m0 >= g_cnt_pad) return; }

    extern __shared__ char smem[];
    uint32_t sb = smem_to_u32(smem);
    const int tid = threadIdx.x;
    const int wid = tid >> 5;
    const int lane = tid & 31;
    const int warp_m = (wid & 1) * 64;     // 2 M-groups of 64
    const int warp_n = (wid >> 1) * 64;    // 2 N-groups of 64

    // MODE 2: per-batch B (Wout * kv[batch]) selected by row block
    const __half* __restrict__ Bp = (MODE == 2)
        ? B + ((size_t)(m0 >> 12) << 20) : B;

    // ldmatrix per-lane address components (validated R2-R15)
    const int lr = lane & 7;
    const int a_row = warp_m + lr + ((lane & 8) ? 8 : 0);
    const int a_ksel = (lane & 16) ? 16 : 0;
    const int b_row = warp_n + lr + ((lane & 16) ? 8 : 0);
    const int b_ksel = (lane & 8) ? 16 : 0;

    float acc[4][8][4];
    #pragma unroll
    for (int i = 0; i < 4; i++)
        #pragma unroll
        for (int j = 0; j < 8; j++)
            #pragma unroll
            for (int k = 0; k < 4; k++) acc[i][j][k] = 0.0f;

    // prologue: stages 0,1
    gemm_issue_load<MODE>(sb, 0, tid, m0, n0, 0,  A, Bp, rmap);
    gemm_issue_load<MODE>(sb, 1, tid, m0, n0, 64, A, Bp, rmap);

    int slot = 0;
    for (int it = 0; it < NKT; it++) {
        if (it == NKT - 1) { CP_ASYNC_WAIT_0(); } else { CP_ASYNC_WAIT_1(); }
        __syncthreads();

        int nt = it + 2;
        if (nt < NKT) {
            int ns = slot + 2; if (ns >= STAGES) ns -= STAGES;
            gemm_issue_load<MODE>(sb, ns, tid, m0, n0, nt << 6, A, Bp, rmap);
        }

        uint32_t ab = sb + slot * STAGE_BYTES;
        uint32_t bb = ab + 16384;

        #pragma unroll
        for (int ks = 0; ks < 4; ks++) {
            uint32_t koff = (uint32_t)(ks << 5);
            uint32_t bfr[8][2];
            #pragma unroll
            for (int nb = 0; nb < 4; nb++) {
                int row = b_row + nb * 16;
                uint32_t addr = bb + (uint32_t)(row << 7)
                              + ((koff + b_ksel) ^ (uint32_t)((row & 7) << 4));
                LDSM_X4(bfr[2 * nb][0], bfr[2 * nb][1],
                        bfr[2 * nb + 1][0], bfr[2 * nb + 1][1], addr);
            }
            uint32_t afr[4][4];
            #pragma unroll
            for (int mf = 0; mf < 4; mf++) {
                int row = a_row + mf * 16;
                uint32_t addr = ab + (uint32_t)(row << 7)
                              + ((koff + a_ksel) ^ (uint32_t)((row & 7) << 4));
                LDSM_X4(afr[mf][0], afr[mf][1], afr[mf][2], afr[mf][3], addr);
            }
            #pragma unroll
            for (int mf = 0; mf < 4; mf++)
                #pragma unroll
                for (int nf = 0; nf < 8; nf++)
                    MMA_16816_F16(acc[mf][nf], afr[mf], bfr[nf]);
        }
        slot++; if (slot >= STAGES) slot = 0;
    }

    // epilogue
    const int gid = lane >> 2;
    const int t4 = lane & 3;
    const int blk = (MODE == 3) ? (n0 >> 10) : 0;   // MODE 3: 0=k, 1=v
    const int nclb = (MODE == 3) ? (n0 & 1023) : n0;
    __half* __restrict__ H = (MODE == 3) ? (blk ? H1 : H0) : H0;
    #pragma unroll
    for (int mf = 0; mf < 4; mf++) {
        int r0 = m0 + warp_m + mf * 16 + gid;
        float iq0 = 1.f, iq1 = 1.f;
        if (MODE == 2) { iq0 = rsqrtf(snorm[r0]); iq1 = rsqrtf(snorm[r0 + 8]); }
        float s0 = 0.f, s1 = 0.f;
        #pragma unroll
        for (int nf = 0; nf < 8; nf++) {
            int c = n0 + warp_n + nf * 8 + t4 * 2;
            float2 b2 = *(const float2*)(bias + c);
            if (MODE == 2) {
                float z00 = acc[mf][nf][0] * iq0 + b2.x;
                float z01 = acc[mf][nf][1] * iq0 + b2.y;
                float z10 = acc[mf][nf][2] * iq1 + b2.x;
                float z11 = acc[mf][nf][3] * iq1 + b2.y;
                *(float2*)(C + (size_t)r0 * N + c) = make_float2(z00, z01);
                *(float2*)(C + (size_t)(r0 + 8) * N + c) = make_float2(z10, z11);
            } else {
                float z00 = acc[mf][nf][0] + b2.x;
                float z01 = acc[mf][nf][1] + b2.y;
                float z10 = acc[mf][nf][2] + b2.x;
                float z11 = acc[mf][nf][3] + b2.y;
                int cl = nclb + warp_n + nf * 8 + t4 * 2;
                *(__half2*)(H + (size_t)r0 * DD_ + cl) = __floats2half2_rn(z00, z01);
                *(__half2*)(H + (size_t)(r0 + 8) * DD_ + cl) = __floats2half2_rn(z10, z11);
                s0 += z00 * z00 + z01 * z01;
                s1 += z10 * z10 + z11 * z11;
            }
        }
        if ((MODE == 1) || (MODE == 3 && blk == 0)) {
            // reduce across the 4 t4-lanes sharing this row pair
            s0 += __shfl_xor_sync(0xffffffffu, s0, 1);
            s0 += __shfl_xor_sync(0xffffffffu, s0, 2);
            s1 += __shfl_xor_sync(0xffffffffu, s1, 1);
            s1 += __shfl_xor_sync(0xffffffffu, s1, 2);
            if (t4 == 0) {
                atomicAdd(snorm + r0, s0);
                atomicAdd(snorm + r0 + 8, s1);
            }
        }
    }
}

// ---------------------------------------------------------------------------
// Elementwise / reduction kernels
// ---------------------------------------------------------------------------

// fp32 -> fp16 convert, 8 elems/thread (x buffer)
__global__ void cvt_f16_kernel(const float* __restrict__ in,
                               __half* __restrict__ out, int n8)
{
    int idx = blockIdx.x * blockDim.x + threadIdx.x;
    if (idx >= n8) return;
    float4 a = ((const float4*)in)[idx * 2];
    float4 b = ((const float4*)in)[idx * 2 + 1];
    union { uint4 u; __half2 h[4]; } r;
    r.h[0] = __floats2half2_rn(a.x, a.y);
    r.h[1] = __floats2half2_rn(a.z, a.w);
    r.h[2] = __floats2half2_rn(b.x, b.y);
    r.h[3] = __floats2half2_rn(b.z, b.w);
    ((uint4*)out)[idx] = r.u;
}

// Both weight matrices in one launch: chunks [0, NWQ) -> Wqkv, rest -> Wout.
#define NWQ_ (E3_ * DD_ / 8)
#define NWO_ (DD_ * DD_ / 8)
__global__ void cvt_w_kernel(const float* __restrict__ wq,
                             const float* __restrict__ wo,
                             __half* __restrict__ wqh,
                             __half* __restrict__ woh)
{
    int idx = blockIdx.x * blockDim.x + threadIdx.x;
    const float* in;
    __half* out;
    int off;
    if (idx < NWQ_) { in = wq; out = wqh; off = idx; }
    else            { in = wo; out = woh; off = idx - NWQ_; }
    float4 a = ((const float4*)in)[off * 2];
    float4 b = ((const float4*)in)[off * 2 + 1];
    union { uint4 u; __half2 h[4]; } r;
    r.h[0] = __floats2half2_rn(a.x, a.y);
    r.h[1] = __floats2half2_rn(a.z, a.w);
    r.h[2] = __floats2half2_rn(b.x, b.y);
    r.h[3] = __floats2half2_rn(b.z, b.w);
    ((uint4*)out)[off] = r.u;
}

// zero accumulators (every graph replay)
__global__ void prep_kernel(float* __restrict__ kv,
                            float* __restrict__ sq, float* __restrict__ sk)
{
    int i = blockIdx.x * blockDim.x + threadIdx.x;
    if (i < BB_ * DD_) kv[i] = 0.0f;
    if (i < MM_) { sq[i] = 0.0f; sk[i] = 0.0f; }
}

// Ordered compaction of unmasked rows + mask dtype detection. 1 block.
__global__ __launch_bounds__(1024) void scan_kernel(
    const unsigned char* __restrict__ m, int* __restrict__ rowmap)
{
    __shared__ int cnts[1024];
    __shared__ int s_any;
    int tid = threadIdx.x;
    if (tid == 0) s_any = 0;
    __syncthreads();
    // dtype detection: int32-encoded 0/1 has zero bytes at offset % 4 != 0
    int det = 0;
    #pragma unroll 4
    for (int j = 0; j < 16; j++) {
        int idx = tid * 16 + j;
        if ((idx & 3) != 0) det |= m[idx];
    }
    if (det) atomicOr(&s_any, 1);
    __syncthreads();
    const int isByte = s_any;
    const int* m32 = (const int*)m;
    // count unmasked rows in this thread's 16-row slice
    unsigned int bits = 0;
    int c = 0;
    for (int j = 0; j < 16; j++) {
        int row = tid * 16 + j;
        bool msk = isByte ? (m[row] != 0) : (m32[row] != 0);
        if (!msk) { bits |= (1u << j); c++; }
    }
    cnts[tid] = c;
    __syncthreads();
    // inclusive Hillis-Steele scan
    for (int off = 1; off < 1024; off <<= 1) {
        int v = (tid >= off) ? cnts[tid - off] : 0;
        __syncthreads();
        cnts[tid] += v;
        __syncthreads();
    }
    int pos = cnts[tid] - c;
    for (int j = 0; j < 16; j++)
        if (bits & (1u << j)) rowmap[pos++] = tid * 16 + j;
    __syncthreads();
    int total = cnts[1023];
    int pad = (total + 127) & ~127;
    if (tid == 0) { g_cnt = total; g_cnt_pad = pad; }
    for (int i = total + tid; i < pad; i += 1024) rowmap[i] = 0;
}

// Compacted k_hat*v reduction into kv[B,D]. Block = 64 compacted slots,
// 256 threads; thread owns dims [4*tid, 4*tid+4). Batch flush on boundary.
__global__ __launch_bounds__(256) void stage2_kernel(
    const __half* __restrict__ kh, const __half* __restrict__ vh,
    const float* __restrict__ sk, const int* __restrict__ rowmap,
    float* __restrict__ kv)
{
    int cnt = g_cnt;
    int R0 = blockIdx.x * 64;
    if (R0 >= cnt) return;
    int lim = cnt - R0; if (lim > 64) lim = 64;
    __shared__ float s_ik[64];
    __shared__ int s_b[64];
    int tid = threadIdx.x;
    if (tid < 64 && tid < lim) {
        s_ik[tid] = rsqrtf(sk[R0 + tid]);
        s_b[tid] = rowmap[R0 + tid] >> 12;
    }
    __syncthreads();

    float ax = 0.f, ay = 0.f, az = 0.f, aw = 0.f;
    int cb = s_b[0];
    for (int r = 0; r < lim; r++) {
        int b = s_b[r];
        if (b != cb) {
            float* kvb = kv + cb * DD_ + tid * 4;
            atomicAdd(kvb + 0, ax); atomicAdd(kvb + 1, ay);
            atomicAdd(kvb + 2, az); atomicAdd(kvb + 3, aw);
            ax = ay = az = aw = 0.f;
            cb = b;
        }
        int slot = R0 + r;
        float ik = s_ik[r];
        union { uint2 u; __half2 h[2]; } kk, vv;
        kk.u = *(const uint2*)(kh + (size_t)slot * DD_ + tid * 4);
        vv.u = *(const uint2*)(vh + (size_t)slot * DD_ + tid * 4);
        float2 k0 = __half22float2(kk.h[0]);
        float2 k1 = __half22float2(kk.h[1]);
        float2 v0 = __half22float2(vv.h[0]);
        float2 v1 = __half22float2(vv.h[1]);
        ax += k0.x * ik * v0.x;
        ay += k0.y * ik * v0.y;
        az += k1.x * ik * v1.x;
        aw += k1.y * ik * v1.y;
    }
    float* kvb = kv + cb * DD_ + tid * 4;
    atomicAdd(kvb + 0, ax); atomicAdd(kvb + 1, ay);
    atomicAdd(kvb + 2, az); atomicAdd(kvb + 3, aw);
}

// Wp[b][n][c] = Wout[n][c] * kv[b][c]  -> fp16. 8 elems/thread.
__global__ __launch_bounds__(256) void build_wp_kernel(
    const __half* __restrict__ woh, const float* __restrict__ kv,
    __half* __restrict__ wp)
{
    int idx = blockIdx.x * blockDim.x + threadIdx.x;   // 8-elem chunk id
    int b = idx >> 17;                // 131072 chunks per batch
    int off = idx & 131071;
    int c = (off & 127) * 8;          // column within row
    union { uint4 u; __half2 h[4]; } w;
    w.u = *(const uint4*)(woh + (size_t)off * 8);
    const float* kp = kv + b * DD_ + c;
    float4 k0 = *(const float4*)(kp);
    float4 k1 = *(const float4*)(kp + 4);
    float2 w0 = __half22float2(w.h[0]);
    float2 w1 = __half22float2(w.h[1]);
    float2 w2 = __half22float2(w.h[2]);
    float2 w3 = __half22float2(w.h[3]);
    union { uint4 u; __half2 h[4]; } r;
    r.h[0] = __floats2half2_rn(w0.x * k0.x, w0.y * k0.y);
    r.h[1] = __floats2half2_rn(w1.x * k0.z, w1.y * k0.w);
    r.h[2] = __floats2half2_rn(w2.x * k1.x, w2.y * k1.y);
    r.h[3] = __floats2half2_rn(w3.x * k1.z, w3.y * k1.w);
    *(uint4*)(wp + (size_t)idx * 8) = r.u;
}

// ---------------------------------------------------------------------------
// Launch
// ---------------------------------------------------------------------------
extern "C" void kernel_launch(void* const* d_in, const int* in_sizes, int n_in,
                              void* d_out, int out_size)
{
    const float* x = (const float*)d_in[0];
    const unsigned char* mask = (const unsigned char*)d_in[1];
    const float* Wqkv = (const float*)d_in[2];
    const float* bqkv = (const float*)d_in[3];
    const float* Wout = (const float*)d_in[4];
    const float* bout = (const float*)d_in[5];
    float* out = (float*)d_out;

    float *p_kv, *p_sq, *p_sk;
    int* p_rowmap;
    __half *p_qh, *p_kh, *p_vh, *p_xh, *p_wqh, *p_woh, *p_wp;
    cudaGetSymbolAddress((void**)&p_kv, g_kv);
    cudaGetSymbolAddress((void**)&p_sq, g_sq);
    cudaGetSymbolAddress((void**)&p_sk, g_sk);
    cudaGetSymbolAddress((void**)&p_rowmap, g_rowmap);
    cudaGetSymbolAddress((void**)&p_qh, g_qh);
    cudaGetSymbolAddress((void**)&p_kh, g_kh);
    cudaGetSymbolAddress((void**)&p_vh, g_vh);
    cudaGetSymbolAddress((void**)&p_xh, g_xh);
    cudaGetSymbolAddress((void**)&p_wqh, g_wqh);
    cudaGetSymbolAddress((void**)&p_woh, g_woh);
    cudaGetSymbolAddress((void**)&p_wp, g_wp);

    cudaFuncSetAttribute(gemm_f16_kernel<1>,
                         cudaFuncAttributeMaxDynamicSharedMemorySize, GS_TOTAL);
    cudaFuncSetAttribute(gemm_f16_kernel<2>,
                         cudaFuncAttributeMaxDynamicSharedMemorySize, GS_TOTAL);
    cudaFuncSetAttribute(gemm_f16_kernel<3>,
                         cudaFuncAttributeMaxDynamicSharedMemorySize, GS_TOTAL);

    // 1: zero accumulators
    prep_kernel<<<MM_ / 256, 256>>>(p_kv, p_sq, p_sk);
    // 2: mask dtype detect + ordered compaction of unmasked rows
    scan_kernel<<<1, 1024>>>(mask, p_rowmap);
    // 3: x -> fp16
    cvt_f16_kernel<<<(MM_ * DD_ / 8 + 255) / 256, 256>>>(x, p_xh, MM_ * DD_ / 8);
    // 4: Wqkv + Wout -> fp16 (single launch)
    cvt_w_kernel<<<(NWQ_ + NWO_ + 255) / 256, 256>>>(Wqkv, Wout, p_wqh, p_woh);
    // 5: q-GEMM: q = x @ Wq^T + bq (all rows), sumsq fused
    gemm_f16_kernel<1><<<dim3(DD_ / 128, MM_ / 128), NTHR, GS_TOTAL>>>(
        p_xh, p_wqh, bqkv, (float*)nullptr, DD_,
        p_qh, (__half*)nullptr, p_sq, (const int*)nullptr);
    // 6: kv-GEMM over compacted rows: k,v = x[rowmap] @ Wkv^T + bkv
    gemm_f16_kernel<3><<<dim3(2 * DD_ / 128, MM_ / 128), NTHR, GS_TOTAL>>>(
        p_xh, p_wqh + (size_t)DD_ * DD_, bqkv + DD_, (float*)nullptr, 2 * DD_,
        p_kh, p_vh, p_sk, p_rowmap);
    // 7: compacted k_hat*v reduction -> kv
    stage2_kernel<<<MM_ / 64, 256>>>(p_kh, p_vh, p_sk, p_rowmap, p_kv);
    // 8: Wp[b] = Wout * kv[b]
    build_wp_kernel<<<BB_ * DD_ * DD_ / 8 / 256, 256>>>(p_woh, p_kv, p_wp);
    // 9: GEMM2: out = rsqrt(sq) * (q @ Wp_b^T) + b_out
    gemm_f16_kernel<2><<<dim3(DD_ / 128, MM_ / 128), NTHR, GS_TOTAL>>>(
        p_qh, p_wp, bout, out, DD_,
        (__half*)nullptr, (__half*)nullptr, p_sq, (const int*)nullptr);
}